// round 17
// baseline (speedup 1.0000x reference)
#include <cuda_runtime.h>
#include <cuda_fp16.h>
#include <mma.h>
#include <cstdint>

using namespace nvcuda;

#define DD   64
#define GSZ  (DD*DD*DD)
#define NMAX 65536
#define CC   32
#define FULLMASK 0xffffffffu
#define GRIDB 148
#define THR   512
#define CONV_THR 320
#define CONV_WARPS 10
#define NTAP_SEG 6
// smem byte layout for k_conv_w
#define OFFW 256
#define WTAPB 5120                      // per tap: hi 2560B + lo 2560B (32x40 halves)
#define OFFS (OFFW + NTAP_SEG * WTAPB)  // 30976
#define STAGEB 9216                     // 64 rows x 144B
#define SMEMB (OFFS + CONV_WARPS * 2 * STAGEB)   // 215296

// ---------------- device scratch ----------------
// Invariants at entry of every kernel_launch: g_grid all-zero, g_acc all-zero
// (k_epi restores both behind itself). g_bar is a monotone ticket.
__device__ int    g_bar;
__device__ int    g_grid[GSZ];                // 0 = empty, else m+1
__device__ int    g_coords[NMAX];
__device__ unsigned int g_pairs[27 * NMAX];   // bucket t: (src<<16)|m
__device__ int    g_cnt[27 * 32];             // padded counters (stride 32)
__device__ float  g_acc[NMAX * CC];
__device__ __half g_fh[NMAX * 64];            // per point: [32 hi][32 lo]

// ---------------- helpers ----------------
__device__ __forceinline__ void red4(float* p, float a, float b, float c, float d) {
    asm volatile("red.global.add.v4.f32 [%0], {%1, %2, %3, %4};"
                 :: "l"(p), "f"(a), "f"(b), "f"(c), "f"(d) : "memory");
}
__device__ __forceinline__ void cp16b(void* smem_dst, const void* gsrc) {
    unsigned d = (unsigned)__cvta_generic_to_shared(smem_dst);
    asm volatile("cp.async.cg.shared.global [%0], [%1], 16;" :: "r"(d), "l"(gsrc));
}
#define CP_COMMIT() asm volatile("cp.async.commit_group;" ::: "memory")
#define CP_WAIT1()  asm volatile("cp.async.wait_group 1;" ::: "memory")

__device__ __forceinline__ void grid_barrier() {
    __syncthreads();
    if (threadIdx.x == 0) {
        __threadfence();
        int ticket = atomicAdd(&g_bar, 1);
        int target = (ticket / GRIDB + 1) * GRIDB;
        volatile int* vb = &g_bar;
        while (*vb < target) { }
    }
    __syncthreads();
}

// ---------------- prep: atomic-free pair building (unchanged from R16) ----------------
__global__ __launch_bounds__(THR, 1)
void k_prep(const void* __restrict__ idx, const float* __restrict__ values, int N) {
    int tid = threadIdx.x;
    int gt  = blockIdx.x * THR + tid;
    int wid = tid >> 5, lane = tid & 31;
    unsigned ltmask = (1u << lane) - 1u;

    __shared__ int w_cnt[16][28];
    __shared__ int s_wbase[16][28];
    __shared__ int s_bbase[28];
    __shared__ int s_is64;

    if (gt < 27 * 32) g_cnt[gt] = 0;
    if (tid < 16 * 28) ((int*)w_cnt)[tid] = 0;

    for (int i = gt; i < N * CC; i += GRIDB * THR) {
        float v = values[i];
        __half h = __float2half_rn(v);
        __half l = __float2half_rn(v - __half2float(h));
        int m = i >> 5, c = i & 31;
        g_fh[m * 64 + c] = h;
        g_fh[m * 64 + 32 + c] = l;
    }

    {
        int v = (tid < 256) ? ((const int*)idx)[2 * tid + 1] : 0;
        int any = __syncthreads_count(v != 0);
        if (tid == 0) s_is64 = (any == 0) ? 1 : 0;
    }
    __syncthreads();
    int is64 = s_is64;

    int m = gt;
    int cp = 0;
    if (m < N) {
        int z, y, x;
        if (is64) {
            const long long* p = (const long long*)idx;
            z = (int)p[m * 4 + 1]; y = (int)p[m * 4 + 2]; x = (int)p[m * 4 + 3];
        } else {
            const int* p = (const int*)idx;
            z = p[m * 4 + 1]; y = p[m * 4 + 2]; x = p[m * 4 + 3];
        }
        cp = (z << 12) | (y << 6) | x;
        g_coords[m] = cp;
        g_grid[cp] = m + 1;
    }
    grid_barrier();

    bool active = (m < N);
    int vv[3] = { (cp >> 12) & 63, (cp >> 6) & 63, cp & 63 };
    int ti[3][3], sv[3][3];
#pragma unroll
    for (int a = 0; a < 3; a++) {
        int v = vv[a];
        if (v == 0) {
            ti[a][0] = 0; sv[a][0] = 0;
            ti[a][1] = 0; sv[a][1] = 1;
            ti[a][2] = 1; sv[a][2] = 0;
        } else if (v == DD - 1) {
            ti[a][0] = 2; sv[a][0] = DD - 2;
            ti[a][1] = 2; sv[a][1] = DD - 1;
            ti[a][2] = 1; sv[a][2] = DD - 1;
        } else {
            ti[a][0] = 0; sv[a][0] = v + 1;
            ti[a][1] = 1; sv[a][1] = v;
            ti[a][2] = 2; sv[a][2] = v - 1;
        }
    }
    int srcs[27];
    int taps[27];
    {
        int slot = 0;
#pragma unroll
        for (int a = 0; a < 3; a++)
#pragma unroll
            for (int b = 0; b < 3; b++)
#pragma unroll
                for (int c = 0; c < 3; c++) {
                    int lin = (sv[0][a] << 12) | (sv[1][b] << 6) | sv[2][c];
                    srcs[slot] = active ? (g_grid[lin] - 1) : -1;
                    taps[slot] = ti[0][a] * 9 + ti[1][b] * 3 + ti[2][c];
                    slot++;
                }
    }

#pragma unroll
    for (int slot = 0; slot < 27; slot++) {
        bool present = srcs[slot] >= 0;
        int t = taps[slot];
        int key = present ? t : (32 + lane);
        unsigned grp = __match_any_sync(FULLMASK, key);
        if (present) {
            int ldr = __ffs(grp) - 1;
            if (lane == ldr) w_cnt[wid][t] += __popc(grp);
        }
    }
    __syncthreads();

    if (tid < 27) {
        int acc = 0;
#pragma unroll
        for (int w = 0; w < 16; w++) {
            s_wbase[w][tid] = acc;
            acc += w_cnt[w][tid];
        }
        s_bbase[tid] = atomicAdd(&g_cnt[tid * 32], acc);
    }
    __syncthreads();
    if (tid < 16 * 28) ((int*)w_cnt)[tid] = 0;
    __syncthreads();

#pragma unroll
    for (int slot = 0; slot < 27; slot++) {
        bool present = srcs[slot] >= 0;
        int t = taps[slot];
        int key = present ? t : (32 + lane);
        unsigned grp = __match_any_sync(FULLMASK, key);
        if (present) {
            int ldr = __ffs(grp) - 1;
            int rank = __popc(grp & ltmask);
            int off = w_cnt[wid][t];
            int pos = s_bbase[t] + s_wbase[wid][t] + off + rank;
            g_pairs[t * NMAX + pos] = ((unsigned)srcs[slot] << 16) | (unsigned)m;
            if (lane == ldr) w_cnt[wid][t] = off + __popc(grp);
        }
        __syncwarp();
    }
}

// ---------------- wmma conv: 64-row supertiles ----------------
__global__ __launch_bounds__(CONV_THR, 1)
void k_conv_w(const float* __restrict__ kern) {
    extern __shared__ char smc[];
    int* s_tb  = (int*)smc;        // 28
    int* s_cnt = s_tb + 28;        // 27
    int tid = threadIdx.x;
    if (tid < 32) {
        int c = (tid < 27) ? g_cnt[tid * 32] : 0;
        int tiles = (c + 63) >> 6;             // 64-row tiles
        int incl = tiles;
#pragma unroll
        for (int o = 1; o < 32; o <<= 1) {
            int v = __shfl_up_sync(FULLMASK, incl, o);
            if (tid >= o) incl += v;
        }
        if (tid < 27) { s_tb[tid] = incl - tiles; s_cnt[tid] = c; }
        if (tid == 31) s_tb[27] = incl;
    }
    __syncthreads();

    int total = s_tb[27];
    int c0 = (int)(((long long)total * blockIdx.x) / gridDim.x);
    int c1 = (int)(((long long)total * (blockIdx.x + 1)) / gridDim.x);
    if (c0 >= c1) return;

    int t_lo = 0;
    while (t_lo < 26 && c0 >= s_tb[t_lo + 1]) t_lo++;
    int t_hi = t_lo;
    while (t_hi < 26 && (c1 - 1) >= s_tb[t_hi + 1]) t_hi++;

    int lane = tid & 31;
    int wloc = tid >> 5;
    char* wbase  = smc + OFFW;
    char* stage0 = smc + OFFS + wloc * (2 * STAGEB);
    char* stage1 = stage0 + STAGEB;
    int grow = lane >> 3, gc = lane & 7;

    for (int seg = t_lo; seg <= t_hi; seg += NTAP_SEG) {
        int segHi = min(seg + NTAP_SEG - 1, t_hi);
        __syncthreads();
        // weights f32 [t][ci][co] -> half hi/lo [co*40+ci] (col-major for wmma B)
        int nel = (segHi - seg + 1) << 10;
        for (int i = tid; i < nel; i += CONV_THR) {
            int tr = i >> 10, r = i & 1023;
            int ci = r >> 5, co = r & 31;
            float v = kern[((seg + tr) << 10) + r];
            __half h = __float2half_rn(v);
            __half l = __float2half_rn(v - __half2float(h));
            __half* wt = (__half*)(wbase + tr * WTAPB);
            wt[co * 40 + ci] = h;
            wt[1280 + co * 40 + ci] = l;
        }
        __syncthreads();

        int r0 = max(c0, s_tb[seg]);
        int r1 = min(c1, s_tb[segHi + 1]);

        int T = r0 + wloc;
        int t = seg, li = 0, cnt = 0;    unsigned pwa = 0, pwb = 0;
        int t2 = seg, li2 = 0, cnt2 = 0; unsigned pw2a = 0, pw2b = 0;
        int cur = 0;
        int tw = -1;
        wmma::fragment<wmma::matrix_b, 16, 16, 16, __half, wmma::col_major> bh[2][2], bl[2][2];

        if (T < r1) {
            while (t < segHi && T >= s_tb[t + 1]) t++;
            li = T - s_tb[t]; cnt = s_cnt[t];
            int idx = (li << 6) + lane;
            pwa = (idx < cnt) ? g_pairs[t * NMAX + idx] : 0u;
            pwb = (idx + 32 < cnt) ? g_pairs[t * NMAX + idx + 32] : 0u;
#pragma unroll
            for (int i = 0; i < 16; i++) {
                unsigned pr = __shfl_sync(FULLMASK, (i < 8) ? pwa : pwb, 4 * (i & 7) + grow);
                cp16b(stage0 + (4 * i + grow) * 144 + gc * 16,
                      (const char*)(g_fh + (size_t)(pr >> 16) * 64) + gc * 16);
            }
            CP_COMMIT();
            int Tn = T + CONV_WARPS;
            if (Tn < r1) {
                t2 = t;
                while (t2 < segHi && Tn >= s_tb[t2 + 1]) t2++;
                li2 = Tn - s_tb[t2]; cnt2 = s_cnt[t2];
                int idx2 = (li2 << 6) + lane;
                pw2a = (idx2 < cnt2) ? g_pairs[t2 * NMAX + idx2] : 0u;
                pw2b = (idx2 + 32 < cnt2) ? g_pairs[t2 * NMAX + idx2 + 32] : 0u;
            }
        }

        while (T < r1) {
            int Tn = T + CONV_WARPS;
            if (Tn < r1) {
                char* nb = cur ? stage0 : stage1;
#pragma unroll
                for (int i = 0; i < 16; i++) {
                    unsigned pr = __shfl_sync(FULLMASK, (i < 8) ? pw2a : pw2b, 4 * (i & 7) + grow);
                    cp16b(nb + (4 * i + grow) * 144 + gc * 16,
                          (const char*)(g_fh + (size_t)(pr >> 16) * 64) + gc * 16);
                }
            }
            CP_COMMIT();

            // prefetch T+2 metadata
            int t3 = t2, li3 = 0, cnt3 = 0; unsigned pw3a = 0, pw3b = 0;
            int Tnn = Tn + CONV_WARPS;
            if (Tnn < r1) {
                while (t3 < segHi && Tnn >= s_tb[t3 + 1]) t3++;
                li3 = Tnn - s_tb[t3]; cnt3 = s_cnt[t3];
                int idx3 = (li3 << 6) + lane;
                pw3a = (idx3 < cnt3) ? g_pairs[t3 * NMAX + idx3] : 0u;
                pw3b = (idx3 + 32 < cnt3) ? g_pairs[t3 * NMAX + idx3 + 32] : 0u;
            }

            CP_WAIT1();
            __syncwarp();
            char* stg = cur ? stage1 : stage0;

            // B frags (per-tap persistent)
            if (t != tw) {
                __half* whb = (__half*)(wbase + (t - seg) * WTAPB);
                __half* wlb = whb + 1280;
#pragma unroll
                for (int ki = 0; ki < 2; ki++)
#pragma unroll
                    for (int ni = 0; ni < 2; ni++) {
                        wmma::load_matrix_sync(bh[ki][ni], whb + ni * 16 * 40 + ki * 16, 40);
                        wmma::load_matrix_sync(bl[ki][ni], wlb + ni * 16 * 40 + ki * 16, 40);
                    }
                tw = t;
            }

            // 4 x 16-row sub-tiles; A frags hi at col 0, lo at col 32; pitch 72 halves
#pragma unroll
            for (int mi = 0; mi < 4; mi++) {
                wmma::fragment<wmma::matrix_a, 16, 16, 16, __half, wmma::row_major> ah[2], al[2];
#pragma unroll
                for (int ki = 0; ki < 2; ki++) {
                    wmma::load_matrix_sync(ah[ki], (__half*)stg + mi * 16 * 72 + ki * 16, 72);
                    wmma::load_matrix_sync(al[ki], (__half*)stg + mi * 16 * 72 + 32 + ki * 16, 72);
                }
                wmma::fragment<wmma::accumulator, 16, 16, 16, float> acc;
#pragma unroll
                for (int ni = 0; ni < 2; ni++) {
                    wmma::fill_fragment(acc, 0.f);
#pragma unroll
                    for (int ki = 0; ki < 2; ki++) {
                        wmma::mma_sync(acc, ah[ki], bh[ki][ni], acc);
                        wmma::mma_sync(acc, ah[ki], bl[ki][ni], acc);
                        wmma::mma_sync(acc, al[ki], bh[ki][ni], acc);
                    }
                    wmma::store_matrix_sync((float*)stg + mi * 16 * 36 + ni * 16, acc, 36,
                                            wmma::mem_row_major);
                }
            }
            __syncwarp();

            // scatter 64 rows via red4
#pragma unroll
            for (int i = 0; i < 16; i++) {
                int row = 4 * i + (lane >> 3);
                int q = lane & 7;
                unsigned prw = __shfl_sync(FULLMASK, (i < 8) ? pwa : pwb,
                                           4 * (i & 7) + (lane >> 3));
                if (((li << 6) + row) < cnt) {
                    float4 v = *(float4*)(stg + row * 144 + q * 16);
                    red4(g_acc + (size_t)(prw & 0xffffu) * CC + q * 4, v.x, v.y, v.z, v.w);
                }
            }

            T = Tn; cur ^= 1;
            t = t2; li = li2; cnt = cnt2; pwa = pw2a; pwb = pw2b;
            t2 = t3; li2 = li3; cnt2 = cnt3; pw2a = pw3a; pw2b = pw3b;
        }
    }
}

// ---------------- epilogue: resets g_acc; optional g_fh emit / grid clear ----------------
__global__ void k_epi(const float* __restrict__ mask, const float* __restrict__ bias,
                      const float* __restrict__ resid, float* __restrict__ outp,
                      int N, int do_relu, int clear_grid, int write_fh) {
    int i = blockIdx.x * blockDim.x + threadIdx.x;
    if (i >= N * 8) return;
    int m = i >> 3, q = i & 7;
    float4 a = ((float4*)g_acc)[i];
    float mk = mask[m];
    float4 b = ((const float4*)bias)[q];
    float4 o;
    o.x = (a.x + mk * b.x) * mk;
    o.y = (a.y + mk * b.y) * mk;
    o.z = (a.z + mk * b.z) * mk;
    o.w = (a.w + mk * b.w) * mk;
    if (do_relu) {
        o.x = fmaxf(o.x, 0.f); o.y = fmaxf(o.y, 0.f);
        o.z = fmaxf(o.z, 0.f); o.w = fmaxf(o.w, 0.f);
    }
    if (resid) {
        float4 r = ((const float4*)resid)[i];
        o.x += r.x; o.y += r.y; o.z += r.z; o.w += r.w;
    }
    if (write_fh) {
        float hx = __half2float(__float2half_rn(o.x));
        float hy = __half2float(__float2half_rn(o.y));
        float hz = __half2float(__float2half_rn(o.z));
        float hw = __half2float(__float2half_rn(o.w));
        __half2* ph = (__half2*)(g_fh + (size_t)m * 64 + q * 4);
        ph[0] = __floats2half2_rn(o.x, o.y);
        ph[1] = __floats2half2_rn(o.z, o.w);
        __half2* pl = (__half2*)(g_fh + (size_t)m * 64 + 32 + q * 4);
        pl[0] = __floats2half2_rn(o.x - hx, o.y - hy);
        pl[1] = __floats2half2_rn(o.z - hz, o.w - hw);
    }
    if (outp) ((float4*)outp)[i] = o;
    ((float4*)g_acc)[i] = make_float4(0.f, 0.f, 0.f, 0.f);
    if (clear_grid && q == 0) g_grid[g_coords[m]] = 0;
}

// ---------------- launch ----------------
extern "C" void kernel_launch(void* const* d_in, const int* in_sizes, int n_in,
                              void* d_out, int out_size)
{
    const float* values = (const float*)d_in[0];
    const void*  indices = d_in[1];
    const float* mask   = (const float*)d_in[2];
    const float* kern1  = (const float*)d_in[3];
    const float* bias1  = (const float*)d_in[4];
    const float* kern2  = (const float*)d_in[5];
    const float* bias2  = (const float*)d_in[6];
    float* out = (float*)d_out;

    int N = in_sizes[0] / CC;
    if (N > NMAX) N = NMAX;

    static int smem_set = 0;
    if (!smem_set) {
        cudaFuncSetAttribute(k_conv_w, cudaFuncAttributeMaxDynamicSharedMemorySize, SMEMB);
        smem_set = 1;
    }

    k_prep<<<GRIDB, THR>>>(indices, values, N);
    k_conv_w<<<GRIDB, CONV_THR, SMEMB>>>(kern1);
    k_epi<<<(N * 8 + 511) / 512, 512>>>(mask, bias1, nullptr, nullptr, N, 1, 1, 1);
    k_conv_w<<<GRIDB, CONV_THR, SMEMB>>>(kern2);
    k_epi<<<(N * 8 + 511) / 512, 512>>>(mask, bias2, values, out, N, 0, 0, 0);
}